// round 3
// baseline (speedup 1.0000x reference)
#include <cuda_runtime.h>

// Problem constants (fixed by setup_inputs)
#define BB 32
#define SS 4096
#define DD 512
#define BITMASK 0xFFF   // 12 bits

__global__ __launch_bounds__(512, 1)
void binpos_kernel(const float* __restrict__ x,
                   const int*   __restrict__ positions,
                   const int*   __restrict__ anchor,
                   const float* __restrict__ read_offset,
                   const int*   __restrict__ input_length,
                   const float* __restrict__ Wv,     // [D, D] row-major (e, d)
                   const float* __restrict__ Wc,     // [8, D] row-major (c, e)
                   float* __restrict__ out_char,     // [B, 8]
                   float* __restrict__ out_off,      // [B]
                   float* __restrict__ out_w)        // [B, S]
{
    const int b   = blockIdx.x;
    const int tid = threadIdx.x;

    __shared__ unsigned char h_arr[SS];
    __shared__ int   sh_min;
    __shared__ int   sh_cnt;
    __shared__ int   sh_list[64];
    __shared__ float t[DD];
    __shared__ float att[DD];

    const int   a  = anchor[b];
    const float ro = read_offset[b];
    const int   L  = input_length[b];

    // query bits: clip(read_offset, 0, 4095) -> integer -> 12-bit pattern
    float v = fminf(fmaxf(ro, 0.0f), 4095.0f);
    const int qi = (int)floorf(v);

    if (tid == 0) { sh_min = 255; sh_cnt = 0; }
    __syncthreads();

    // ---- Phase 1: hamming distance per position, masked; block min ----
    int local_min = 255;
    for (int s = tid; s < SS; s += blockDim.x) {
        int pos = positions[(size_t)b * SS + s];
        int rel = pos - a - 1;
        rel = min(max(rel, 0), 4095);
        int h = __popc((rel ^ qi) & BITMASK);
        bool m = (pos > a) && (pos <= a + L);
        int hv = m ? h : 255;
        h_arr[s] = (unsigned char)hv;
        local_min = min(local_min, hv);
    }
    atomicMin(&sh_min, local_min);
    __syncthreads();
    const int hmin = sh_min;

    // ---- count matches + build gather list ----
    for (int s = tid; s < SS; s += blockDim.x) {
        if ((int)h_arr[s] == hmin) {
            int idx = atomicAdd(&sh_cnt, 1);
            if (idx < 64) sh_list[idx] = s;
        }
    }
    __syncthreads();
    const int   n     = sh_cnt;
    const float inv_n = 1.0f / (float)n;

    // ---- write softmax weights (exactly 1/n on argmin set, 0 elsewhere) ----
    for (int s = tid; s < SS; s += blockDim.x) {
        out_w[(size_t)b * SS + s] = ((int)h_arr[s] == hmin) ? inv_n : 0.0f;
    }

    // ---- Phase 2: t[d] = sum_s w[s] * x[b,s,d]  (only matching rows) ----
    if (n <= 64) {
        for (int d = tid; d < DD; d += blockDim.x) {
            float acc = 0.0f;
            for (int i = 0; i < n; i++)
                acc += x[((size_t)b * SS + sh_list[i]) * DD + d];
            t[d] = acc * inv_n;
        }
    } else {
        for (int d = tid; d < DD; d += blockDim.x) {
            float acc = 0.0f;
            for (int s = 0; s < SS; s++)
                if ((int)h_arr[s] == hmin)
                    acc += x[((size_t)b * SS + s) * DD + d];
            t[d] = acc * inv_n;
        }
    }
    __syncthreads();

    // ---- Phase 3: att[e] = sum_d t[d] * Wv[e,d] ----
    for (int e = tid; e < DD; e += blockDim.x) {
        const float4* wrow = (const float4*)(Wv + (size_t)e * DD);
        float acc = 0.0f;
        #pragma unroll 8
        for (int d4 = 0; d4 < DD / 4; d4++) {
            float4 w4 = wrow[d4];
            acc += t[d4 * 4 + 0] * w4.x + t[d4 * 4 + 1] * w4.y
                 + t[d4 * 4 + 2] * w4.z + t[d4 * 4 + 3] * w4.w;
        }
        att[e] = acc;
    }
    __syncthreads();

    // ---- Phase 4: char_value[c] = sum_e att[e] * Wc[c,e]; 8 warps, 1 c each ----
    const int warp = tid >> 5;
    const int lane = tid & 31;
    if (warp < 8) {
        float acc = 0.0f;
        for (int e = lane; e < DD; e += 32)
            acc += att[e] * Wc[warp * DD + e];
        #pragma unroll
        for (int off = 16; off > 0; off >>= 1)
            acc += __shfl_down_sync(0xffffffffu, acc, off);
        if (lane == 0) out_char[b * 8 + warp] = acc;
    }

    if (tid == 0) out_off[b] = ro + 1.0f;
}

extern "C" void kernel_launch(void* const* d_in, const int* in_sizes, int n_in,
                              void* d_out, int out_size)
{
    const float* x    = (const float*)d_in[0];   // [B,S,D] f32
    const int*   pos  = (const int*)  d_in[1];   // [B,S] i32
    const int*   anc  = (const int*)  d_in[2];   // [B] i32
    const float* ro   = (const float*)d_in[3];   // [B] f32
    const int*   ilen = (const int*)  d_in[4];   // [B] i32
    const float* Wv   = (const float*)d_in[5];   // [D,D] f32
    const float* Wc   = (const float*)d_in[6];   // [8,D] f32

    float* out = (float*)d_out;
    // Tuple-order flattened output: char_value[B,8] | new_offset[B] | weights[B,1,S]
    float* out_char = out;
    float* out_off  = out + BB * 8;
    float* out_w    = out + BB * 8 + BB;

    binpos_kernel<<<BB, 512>>>(x, pos, anc, ro, ilen, Wv, Wc,
                               out_char, out_off, out_w);
}

// round 6
// speedup vs baseline: 1.6435x; 1.6435x over previous
#include <cuda_runtime.h>

// Problem constants (fixed by setup_inputs)
#define BB 32
#define SS 4096
#define DD 512
#define BITMASK 0xFFF          // 12 bits
#define NCHUNK 8
#define ROWS_PER_CHUNK (DD / NCHUNK)   // 64 rows of Wv per block

// Scratch (device globals: allocation-free). g_cnt is monotonic across launches:
// each launch adds exactly NCHUNK per batch, so (old % NCHUNK)==NCHUNK-1
// identifies the last-arriving block of THIS launch. No reset needed.
__device__ float        g_att[BB * DD];
__device__ unsigned int g_cnt[BB];

__global__ __launch_bounds__(512, 2)
void binpos_fused(const float* __restrict__ x,
                  const int*   __restrict__ positions,
                  const int*   __restrict__ anchor,
                  const float* __restrict__ read_offset,
                  const int*   __restrict__ input_length,
                  const float* __restrict__ Wv,     // [D, D] (e, d)
                  const float* __restrict__ Wc,     // [8, D] (c, e)
                  float* __restrict__ out_char,     // [B, 8]
                  float* __restrict__ out_off,      // [B]
                  float* __restrict__ out_w)        // [B, S]
{
    const int chunk = blockIdx.x;      // 0..7  : which 64-row slice of Wv / weights slice
    const int b     = blockIdx.y;      // 0..31 : batch
    const int tid   = threadIdx.x;     // 0..511

    // 16B alignment REQUIRED: written as unsigned int (4B) in phase 1.
    __shared__ __align__(16) unsigned char h_arr[SS];
    __shared__ int   sh_min;
    __shared__ int   sh_cnt;
    __shared__ int   sh_list[64];
    __shared__ __align__(16) float t[DD];
    __shared__ int   sh_last;

    const int   a  = anchor[b];
    const float ro = read_offset[b];
    const int   L  = input_length[b];

    // query bit pattern: clip(read_offset, 0, 4095) -> integer
    const int qi = (int)floorf(fminf(fmaxf(ro, 0.0f), 4095.0f));

    if (tid == 0) { sh_min = 255; sh_cnt = 0; }
    __syncthreads();

    // ---- Phase 1: hamming per position (vectorized int4 scan), block min ----
    {
        const int4* pos4 = (const int4*)(positions + (size_t)b * SS);
        unsigned int* h4 = (unsigned int*)h_arr;
        int local_min = 255;
        #pragma unroll
        for (int i = tid; i < SS / 4; i += 512) {   // 2 iterations
            int4 p = pos4[i];
            unsigned int packed = 0;
            int pv[4] = {p.x, p.y, p.z, p.w};
            #pragma unroll
            for (int k = 0; k < 4; k++) {
                int rel = min(max(pv[k] - a - 1, 0), 4095);
                int h   = __popc((rel ^ qi) & BITMASK);
                bool m  = (pv[k] > a) && (pv[k] <= a + L);
                int hv  = m ? h : 255;
                packed |= ((unsigned int)hv) << (8 * k);
                local_min = min(local_min, hv);
            }
            h4[i] = packed;
        }
        // warp-level min, then one shared atomic per warp
        local_min = __reduce_min_sync(0xffffffffu, local_min);
        if ((tid & 31) == 0) atomicMin(&sh_min, local_min);
    }
    __syncthreads();
    const int hmin = sh_min;

    // ---- match count + gather list ----
    #pragma unroll
    for (int s = tid; s < SS; s += 512) {
        if ((int)h_arr[s] == hmin) {
            int idx = atomicAdd(&sh_cnt, 1);
            if (idx < 64) sh_list[idx] = s;
        }
    }
    __syncthreads();
    const int   n     = sh_cnt;
    const float inv_n = 1.0f / (float)n;

    // ---- weights slice: this block writes s in [chunk*512, chunk*512+512) ----
    {
        int s = chunk * 512 + tid;
        out_w[(size_t)b * SS + s] = ((int)h_arr[s] == hmin) ? inv_n : 0.0f;
    }

    // ---- Phase 2: t[d] = inv_n * sum over matching rows of x ----
    if (n <= 64) {
        float acc = 0.0f;
        for (int i = 0; i < n; i++)
            acc += x[((size_t)b * SS + sh_list[i]) * DD + tid];
        t[tid] = acc * inv_n;
    } else {
        float acc = 0.0f;
        for (int s = 0; s < SS; s++)
            if ((int)h_arr[s] == hmin)
                acc += x[((size_t)b * SS + s) * DD + tid];
        t[tid] = acc * inv_n;
    }
    __syncthreads();

    // ---- Phase 3: att[e] for 64 rows; 8 threads per row, 64 d's each ----
    {
        const int r    = tid >> 3;          // 0..63  local row
        const int part = tid & 7;           // 0..7   d-slice
        const int e    = chunk * ROWS_PER_CHUNK + r;
        const float4* wrow = (const float4*)(Wv + (size_t)e * DD) + part * 16;
        const float4* t4   = (const float4*)t + part * 16;
        float acc = 0.0f;
        #pragma unroll
        for (int j = 0; j < 16; j++) {
            float4 w4 = wrow[j];
            float4 tv = t4[j];
            acc += tv.x * w4.x + tv.y * w4.y + tv.z * w4.z + tv.w * w4.w;
        }
        // reduce over the 8 contiguous lanes of this row
        acc += __shfl_down_sync(0xffffffffu, acc, 4, 8);
        acc += __shfl_down_sync(0xffffffffu, acc, 2, 8);
        acc += __shfl_down_sync(0xffffffffu, acc, 1, 8);
        if (part == 0) g_att[b * DD + e] = acc;
    }

    if (chunk == 0 && tid == 0) out_off[b] = ro + 1.0f;

    // ---- last-block-per-batch does the 8x512 W_char GEMV ----
    __threadfence();              // publish g_att stores
    __syncthreads();
    if (tid == 0) {
        unsigned int old = atomicAdd(&g_cnt[b], 1u);
        sh_last = ((old % NCHUNK) == (NCHUNK - 1)) ? 1 : 0;
    }
    __syncthreads();

    if (sh_last) {
        __threadfence();          // acquire: see all chunks' g_att
        const int warp = tid >> 5;
        const int lane = tid & 31;
        if (warp < 8) {
            float acc = 0.0f;
            #pragma unroll 4
            for (int e = lane; e < DD; e += 32)
                acc += g_att[b * DD + e] * Wc[warp * DD + e];
            #pragma unroll
            for (int off = 16; off > 0; off >>= 1)
                acc += __shfl_down_sync(0xffffffffu, acc, off);
            if (lane == 0) out_char[b * 8 + warp] = acc;
        }
    }
}

extern "C" void kernel_launch(void* const* d_in, const int* in_sizes, int n_in,
                              void* d_out, int out_size)
{
    const float* x    = (const float*)d_in[0];   // [B,S,D] f32
    const int*   pos  = (const int*)  d_in[1];   // [B,S] i32
    const int*   anc  = (const int*)  d_in[2];   // [B] i32
    const float* ro   = (const float*)d_in[3];   // [B] f32
    const int*   ilen = (const int*)  d_in[4];   // [B] i32
    const float* Wv   = (const float*)d_in[5];   // [D,D] f32
    const float* Wc   = (const float*)d_in[6];   // [8,D] f32

    float* out = (float*)d_out;
    // Tuple-order flattened output: char_value[B,8] | new_offset[B] | weights[B,1,S]
    float* out_char = out;
    float* out_off  = out + BB * 8;
    float* out_w    = out + BB * 8 + BB;

    dim3 grid(NCHUNK, BB);
    binpos_fused<<<grid, 512>>>(x, pos, anc, ro, ilen, Wv, Wc,
                                out_char, out_off, out_w);
}

// round 9
// speedup vs baseline: 3.4311x; 2.0877x over previous
#include <cuda_runtime.h>

// Problem constants (fixed by setup_inputs)
#define BB 32
#define SS 4096
#define DD 512
#define BITMASK 0xFFF          // 12 bits
#define NCHUNK 8
#define ROWS_PER_CHUNK (DD / NCHUNK)   // 64 rows of Wv per block

// Scratch (device globals: allocation-free). g_cnt is monotonic across launches:
// each launch adds exactly NCHUNK per batch, so (old % NCHUNK)==NCHUNK-1
// identifies the last-arriving block of THIS launch. No reset needed.
__device__ float        g_att[BB * DD];
__device__ unsigned int g_cnt[BB];

__global__ __launch_bounds__(512, 2)
void binpos_fused(const float* __restrict__ x,
                  const int*   __restrict__ positions,
                  const int*   __restrict__ anchor,
                  const float* __restrict__ read_offset,
                  const int*   __restrict__ input_length,
                  const float* __restrict__ Wv,     // [D, D] (e, d)
                  const float* __restrict__ Wc,     // [8, D] (c, e)
                  float* __restrict__ out_char,     // [B, 8]
                  float* __restrict__ out_off,      // [B]
                  float* __restrict__ out_w)        // [B, S]
{
    const int chunk = blockIdx.x;      // 0..7  : which 64-row slice of Wv / weights slice
    const int b     = blockIdx.y;      // 0..31 : batch
    const int tid   = threadIdx.x;     // 0..511

    // 16B alignment REQUIRED: written as unsigned int (4B) in phase 1.
    __shared__ __align__(16) unsigned char h_arr[SS];
    __shared__ int   sh_min;
    __shared__ int   sh_cnt;
    __shared__ int   sh_list[64];
    __shared__ __align__(16) float t[DD];
    __shared__ int   sh_last;

    const int   a  = anchor[b];
    const float ro = read_offset[b];
    const int   L  = input_length[b];

    // query bit pattern: clip(read_offset, 0, 4095) -> integer
    const int qi = (int)floorf(fminf(fmaxf(ro, 0.0f), 4095.0f));

    if (tid == 0) { sh_min = 255; sh_cnt = 0; }
    __syncthreads();

    // ---- Phase 1: hamming per position (vectorized int4 scan), block min ----
    {
        const int4* pos4 = (const int4*)(positions + (size_t)b * SS);
        unsigned int* h4 = (unsigned int*)h_arr;
        int local_min = 255;
        #pragma unroll
        for (int i = tid; i < SS / 4; i += 512) {   // 2 iterations
            int4 p = pos4[i];
            unsigned int packed = 0;
            int pv[4] = {p.x, p.y, p.z, p.w};
            #pragma unroll
            for (int k = 0; k < 4; k++) {
                int rel = min(max(pv[k] - a - 1, 0), 4095);
                int h   = __popc((rel ^ qi) & BITMASK);
                bool m  = (pv[k] > a) && (pv[k] <= a + L);
                int hv  = m ? h : 255;
                packed |= ((unsigned int)hv) << (8 * k);
                local_min = min(local_min, hv);
            }
            h4[i] = packed;
        }
        // warp-level min, then one shared atomic per warp
        local_min = __reduce_min_sync(0xffffffffu, local_min);
        if ((tid & 31) == 0) atomicMin(&sh_min, local_min);
    }
    __syncthreads();
    const int hmin = sh_min;

    // ---- match count + gather list ----
    #pragma unroll
    for (int s = tid; s < SS; s += 512) {
        if ((int)h_arr[s] == hmin) {
            int idx = atomicAdd(&sh_cnt, 1);
            if (idx < 64) sh_list[idx] = s;
        }
    }
    __syncthreads();
    const int   n     = sh_cnt;
    const float inv_n = 1.0f / (float)n;

    // ---- weights slice: this block writes s in [chunk*512, chunk*512+512) ----
    {
        int s = chunk * 512 + tid;
        out_w[(size_t)b * SS + s] = ((int)h_arr[s] == hmin) ? inv_n : 0.0f;
    }

    // ---- Phase 2: t[d] = inv_n * sum over matching rows of x ----
    if (n <= 64) {
        float acc = 0.0f;
        for (int i = 0; i < n; i++)
            acc += x[((size_t)b * SS + sh_list[i]) * DD + tid];
        t[tid] = acc * inv_n;
    } else {
        float acc = 0.0f;
        for (int s = 0; s < SS; s++)
            if ((int)h_arr[s] == hmin)
                acc += x[((size_t)b * SS + s) * DD + tid];
        t[tid] = acc * inv_n;
    }
    __syncthreads();

    // ---- Phase 3: att[e] for 64 rows; 8 threads per row, INTERLEAVED so a
    //      warp's 8-lane row-groups each read one contiguous 128B line ----
    {
        const int r    = tid >> 3;          // 0..63  local row
        const int part = tid & 7;           // 0..7   lane-within-row
        const int e    = chunk * ROWS_PER_CHUNK + r;
        const float4* wrow = (const float4*)(Wv + (size_t)e * DD);
        const float4* t4   = (const float4*)t;
        float acc0 = 0.0f, acc1 = 0.0f;
        #pragma unroll
        for (int j = 0; j < 16; j += 2) {
            float4 w4a = wrow[j * 8 + part];
            float4 ta  = t4  [j * 8 + part];
            float4 w4b = wrow[(j + 1) * 8 + part];
            float4 tb  = t4  [(j + 1) * 8 + part];
            acc0 += ta.x * w4a.x + ta.y * w4a.y + ta.z * w4a.z + ta.w * w4a.w;
            acc1 += tb.x * w4b.x + tb.y * w4b.y + tb.z * w4b.z + tb.w * w4b.w;
        }
        float acc = acc0 + acc1;
        // reduce over the 8 contiguous lanes of this row
        acc += __shfl_down_sync(0xffffffffu, acc, 4, 8);
        acc += __shfl_down_sync(0xffffffffu, acc, 2, 8);
        acc += __shfl_down_sync(0xffffffffu, acc, 1, 8);
        if (part == 0) g_att[b * DD + e] = acc;
    }

    if (chunk == 0 && tid == 0) out_off[b] = ro + 1.0f;

    // ---- last-block-per-batch does the 8x512 W_char GEMV ----
    __threadfence();              // publish g_att stores
    __syncthreads();
    if (tid == 0) {
        unsigned int old = atomicAdd(&g_cnt[b], 1u);
        sh_last = ((old % NCHUNK) == (NCHUNK - 1)) ? 1 : 0;
    }
    __syncthreads();

    if (sh_last) {
        __threadfence();          // acquire: see all chunks' g_att
        const int warp = tid >> 5;
        const int lane = tid & 31;
        if (warp < 8) {
            float acc = 0.0f;
            #pragma unroll 4
            for (int e = lane; e < DD; e += 32)
                acc += g_att[b * DD + e] * Wc[warp * DD + e];
            #pragma unroll
            for (int off = 16; off > 0; off >>= 1)
                acc += __shfl_down_sync(0xffffffffu, acc, off);
            if (lane == 0) out_char[b * 8 + warp] = acc;
        }
    }
}

extern "C" void kernel_launch(void* const* d_in, const int* in_sizes, int n_in,
                              void* d_out, int out_size)
{
    const float* x    = (const float*)d_in[0];   // [B,S,D] f32
    const int*   pos  = (const int*)  d_in[1];   // [B,S] i32
    const int*   anc  = (const int*)  d_in[2];   // [B] i32
    const float* ro   = (const float*)d_in[3];   // [B] f32
    const int*   ilen = (const int*)  d_in[4];   // [B] i32
    const float* Wv   = (const float*)d_in[5];   // [D,D] f32
    const float* Wc   = (const float*)d_in[6];   // [8,D] f32

    float* out = (float*)d_out;
    // Tuple-order flattened output: char_value[B,8] | new_offset[B] | weights[B,1,S]
    float* out_char = out;
    float* out_off  = out + BB * 8;
    float* out_w    = out + BB * 8 + BB;

    dim3 grid(NCHUNK, BB);
    binpos_fused<<<grid, 512>>>(x, pos, anc, ro, ilen, Wv, Wc,
                                out_char, out_off, out_w);
}